// round 17
// baseline (speedup 1.0000x reference)
#include <cuda_runtime.h>
#include <cuda_fp16.h>

// FernSparseTable v12: 1024-thread CTAs (32 warps/SM) for 2x latency hiding.
//  Thread = (pixel-slot, D-half): acc[32] fp32 per thread. Warp (grp, dh) gathers
//  16B d-slices: 8 px per LDS.128, 4 groups x 8 probes. B values staged in smem
//  (cp.async double-buffer) to keep regs <= 64. Single 128KB fp16 table, bulk-filled
//  per fern (fill issue overlaps phase-1 between two per-fern __syncthreads).

#define TPB 1024
#define NPX 131072
#define NCTA 296
#define PX_PER 443                   // ceil(131072/296); last CTA gets 387
#define TAB_BYTES 131072             // 1024 rows * 128 B
#define PAR_OFF 131072
#define PAR_STRIDE 80                // 8 probes * 8B + 16B pad
#define STAGE0_OFF 172032            // PAR_OFF + 512*80
#define STAGE_BYTES 22528            // 512 px * 11 floats * 4B
#define STAGE1_OFF (STAGE0_OFF + STAGE_BYTES)      // 194560
#define MBAR_OFF   (STAGE1_OFF + STAGE_BYTES)      // 217088
#define SMEM_BYTES (MBAR_OFF + 16)                 // 217104

__device__ __align__(128) __half g_W16[16 * 1024 * 64];

__global__ void cvt_kernel(const float4* __restrict__ W)
{
    int i = blockIdx.x * blockDim.x + threadIdx.x;   // 262144 float4
    float4 v = W[i];
    __half2 a = __floats2half2_rn(v.x, v.y);
    __half2 b = __floats2half2_rn(v.z, v.w);
    uint2 r;
    r.x = *reinterpret_cast<unsigned*>(&a);
    r.y = *reinterpret_cast<unsigned*>(&b);
    reinterpret_cast<uint2*>(g_W16)[i] = r;
}

__device__ __forceinline__ __half2 u2h2(unsigned u) {
    return *reinterpret_cast<__half2*>(&u);
}

extern __shared__ char smem_raw[];

__device__ __forceinline__ void mbar_wait(unsigned mbar, unsigned parity)
{
    unsigned done;
    asm volatile(
        "{\n\t.reg .pred p;\n\t"
        "mbarrier.try_wait.parity.acquire.cta.shared::cta.b64 p, [%1], %2;\n\t"
        "selp.b32 %0, 1, 0, p;\n\t}"
        : "=r"(done) : "r"(mbar), "r"(parity) : "memory");
    if (!done) {
        asm volatile(
            "{\n\t.reg .pred P1;\n\t"
            "WL_%=:\n\t"
            "mbarrier.try_wait.parity.acquire.cta.shared::cta.b64 P1, [%0], %1, 0x989680;\n\t"
            "@P1 bra.uni WD_%=;\n\t"
            "bra.uni WL_%=;\n\t"
            "WD_%=:\n\t}"
            :: "r"(mbar), "r"(parity) : "memory");
    }
}

__global__ __launch_bounds__(TPB, 1)
void fern_kernel(const float* __restrict__ B,
                 const float* __restrict__ bias,
                 float* __restrict__ out)
{
    char*  s_par = smem_raw + PAR_OFF;
    float* s_st0 = (float*)(smem_raw + STAGE0_OFF);
    float* s_st1 = (float*)(smem_raw + STAGE1_OFF);
    float* s_out = (float*)smem_raw;         // epilogue reuse (133KB < STAGE0_OFF... ok: 133120 < 172032)

    const int tid  = threadIdx.x;
    const int lane = tid & 31;
    const int warp = tid >> 5;               // 0..31
    const int wgrp = warp & 15;              // pixel group of warp
    const int dh   = warp >> 4;              // 0 or 1 (d-half)
    const int pxslot = tid & 511;

    const int base = blockIdx.x * PX_PER;
    const int cnt  = min(PX_PER, NPX - base);       // 443 or 387
    const int px   = min(base + pxslot, NPX - 1);   // clamped pixel id
    const bool valid = pxslot < cnt;
    const int n  = px >> 12;
    const int hw = px & 4095;
    const int rem = cnt - wgrp * 32;                // per-warp-group tail bound

    unsigned smem_u32 = (unsigned)__cvta_generic_to_shared(smem_raw);
    const unsigned mbar = smem_u32 + MBAR_OFF;

    if (tid == 0) {
        asm volatile("mbarrier.init.shared.b64 [%0], 1;" :: "r"(mbar) : "memory");
        asm volatile("fence.proxy.async.shared::cta;" ::: "memory");
    }

    const float* Bb = B + (n * 160) * 4096 + hw;
    const unsigned long long Wg =
        (unsigned long long)__cvta_generic_to_global(g_W16);

    float acc[32];
    #pragma unroll
    for (int i = 0; i < 32; ++i) acc[i] = 0.f;

    // lane's 16B d-slice within its 64B half-row
    const char* gl = smem_raw + dh * 64 + (lane & 3) * 16;
    const int px_sub = lane >> 2;            // 0..7

    auto issue_fill = [&](int f) {
        asm volatile("mbarrier.arrive.expect_tx.shared.b64 _, [%0], %1;"
                     :: "r"(mbar), "r"(TAB_BYTES) : "memory");
        unsigned long long src = Wg + (unsigned long long)f * 131072ull;
        #pragma unroll
        for (int c = 0; c < 4; ++c) {
            asm volatile(
                "cp.async.bulk.shared::cta.global.mbarrier::complete_tx::bytes "
                "[%0], [%1], %2, [%3];"
                :: "r"(smem_u32 + c * 32768), "l"(src + c * 32768ull),
                   "r"(32768), "r"(mbar) : "memory");
        }
    };

    // phase-1 (dh==0 threads only): fern logic from staged B -> params
    auto phase1 = [&](const float* sp) {
        float tv[10];
        #pragma unroll
        for (int k = 0; k < 10; ++k) tv[k] = sp[k];

        int wb = 0;
        float bsp = 1.f;
        #pragma unroll
        for (int k = 0; k < 10; ++k) {
            if (tv[k] >= 0.5f) wb |= (1 << k);
            bsp *= fmaxf(tv[k], 1.f - tv[k]);
        }
        int abi0, abi1, abi2;
        float av0, av1, av2;
        {
            float best = fabsf(tv[0] - 0.5f); int bi = 0; float bt = tv[0];
            #pragma unroll
            for (int k = 1; k < 10; ++k) {
                float ak = fabsf(tv[k] - 0.5f);
                if (ak < best) { best = ak; bi = k; bt = tv[k]; }
            }
            abi0 = bi; av0 = bt;
        }
        {
            float best = 3.0e38f; int bi = 0; float bt = 0.f;
            #pragma unroll
            for (int k = 0; k < 10; ++k) {
                float ak = fabsf(tv[k] - 0.5f);
                if (k != abi0 && ak < best) { best = ak; bi = k; bt = tv[k]; }
            }
            abi1 = bi; av1 = bt;
        }
        {
            float best = 3.0e38f; int bi = 0; float bt = 0.f;
            #pragma unroll
            for (int k = 0; k < 10; ++k) {
                float ak = fabsf(tv[k] - 0.5f);
                if (k != abi0 && k != abi1 && ak < best) { best = ak; bi = k; bt = tv[k]; }
            }
            abi2 = bi; av2 = bt;
        }

        const float d0 = 1.f - av0, d1 = 1.f - av1, d2 = 1.f - av2;
        const float denom = fmaxf(av0, d0) * fmaxf(av1, d1) * fmaxf(av2, d2);
        const float bspp = valid ? (bsp / denom) : 0.f;

        float cp[8];
        {
            float g0 = bspp * d0,  g1 = bspp * av0;
            float c00 = g0 * d1,  c10 = g1 * d1;
            float c01 = g0 * av1, c11 = g1 * av1;
            cp[0] = c00 * d2;  cp[1] = c10 * d2;  cp[2] = c01 * d2;  cp[3] = c11 * d2;
            cp[4] = c00 * av2; cp[5] = c10 * av2; cp[6] = c01 * av2; cp[7] = c11 * av2;
        }
        unsigned ch[8];
        #pragma unroll
        for (int j = 0; j < 8; ++j) {
            __half2 hh = __floats2half2_rn(cp[j], cp[j]);
            ch[j] = *reinterpret_cast<unsigned*>(&hh);
        }
        int io[8];
        {
            const int m0 = 1 << abi0, m1 = 1 << abi1, m2 = 1 << abi2;
            const int b0 = wb & ~(m0 | m1 | m2);
            const int i0 = b0, i1 = b0 | m0, i2 = b0 | m1, i3 = b0 | m0 | m1;
            io[0] = i0 << 7;        io[1] = i1 << 7;
            io[2] = i2 << 7;        io[3] = i3 << 7;
            io[4] = (i0 | m2) << 7; io[5] = (i1 | m2) << 7;
            io[6] = (i2 | m2) << 7; io[7] = (i3 | m2) << 7;
        }
        uint4* myp = (uint4*)(s_par + pxslot * PAR_STRIDE);
        #pragma unroll
        for (int jj = 0; jj < 4; ++jj)
            myp[jj] = make_uint4(ch[2*jj], (unsigned)io[2*jj],
                                 ch[2*jj+1], (unsigned)io[2*jj+1]);
    };

    // ---- prologue: stage B(0)->st0, B(1)->st1 (direct); phase1(fern0); fill(0) ----
    if (dh == 0) {
        float* d0p = s_st0 + pxslot * 11;
        float* d1p = s_st1 + pxslot * 11;
        #pragma unroll
        for (int k = 0; k < 10; ++k) {
            d0p[k] = Bb[k * 4096];
            d1p[k] = Bb[40960 + k * 4096];
        }
        phase1(s_st0 + pxslot * 11);
    }
    __syncthreads();            // mbar init + params(0) + staging visible
    if (tid == 0) issue_fill(0);

    #pragma unroll 1
    for (int m = 0; m < 16; ++m) {
        mbar_wait(mbar, (unsigned)(m & 1));

        // ---- phase 2: 8 px per LDS.128, HFMA2; 4 groups ----
        #pragma unroll
        for (int g = 0; g < 4; ++g) {
            if (g * 8 < rem) {                    // warp-uniform guard
                const uint4* pp =
                    (const uint4*)(s_par + (wgrp * 32 + g * 8 + px_sub) * PAR_STRIDE);
                __half2 h0 = __floats2half2_rn(0.f, 0.f);
                __half2 h1 = h0, h2 = h0, h3 = h0;
                #pragma unroll
                for (int jj = 0; jj < 4; ++jj) {
                    uint4 pr = pp[jj];
                    {
                        __half2 c = u2h2(pr.x);
                        uint4 w4 = *(const uint4*)(gl + pr.y);
                        h0 = __hfma2(c, u2h2(w4.x), h0);
                        h1 = __hfma2(c, u2h2(w4.y), h1);
                        h2 = __hfma2(c, u2h2(w4.z), h2);
                        h3 = __hfma2(c, u2h2(w4.w), h3);
                    }
                    {
                        __half2 c = u2h2(pr.z);
                        uint4 w4 = *(const uint4*)(gl + pr.w);
                        h0 = __hfma2(c, u2h2(w4.x), h0);
                        h1 = __hfma2(c, u2h2(w4.y), h1);
                        h2 = __hfma2(c, u2h2(w4.z), h2);
                        h3 = __hfma2(c, u2h2(w4.w), h3);
                    }
                }
                float2 f0 = __half22float2(h0);
                float2 f1 = __half22float2(h1);
                float2 f2 = __half22float2(h2);
                float2 f3 = __half22float2(h3);
                acc[g*8+0] += f0.x; acc[g*8+1] += f0.y;
                acc[g*8+2] += f1.x; acc[g*8+3] += f1.y;
                acc[g*8+4] += f2.x; acc[g*8+5] += f2.y;
                acc[g*8+6] += f3.x; acc[g*8+7] += f3.y;
            }
        }

        if (m < 15) {
            __syncthreads();                    // table + params(m) fully consumed
            if (tid == 0) issue_fill(m + 1);    // overlaps phase1 below

            if (dh == 0) {
                // B(m+1) staged: group committed at fern m-1 (or prologue)
                asm volatile("cp.async.wait_group 0;" ::: "memory");
                phase1(((m + 1) & 1) ? (s_st1 + pxslot * 11)
                                     : (s_st0 + pxslot * 11));
                if (m < 14) {
                    // prefetch B(m+2) -> stage[m&1] (freed: held B(m), consumed last fern)
                    unsigned dst = smem_u32 + ((m & 1) ? STAGE1_OFF : STAGE0_OFF)
                                   + pxslot * 44;
                    const float* src = Bb + (m + 2) * 40960;
                    #pragma unroll
                    for (int k = 0; k < 10; ++k) {
                        asm volatile("cp.async.ca.shared.global [%0], [%1], 4;"
                                     :: "r"(dst + k * 4), "l"(src + k * 4096)
                                     : "memory");
                    }
                    asm volatile("cp.async.commit_group;" ::: "memory");
                }
            }
            __syncthreads();                    // params(m+1) visible to all warps
        }
    }

    // ---- epilogue: stride-65 transpose -> coalesced stores ----
    __syncthreads();
    #pragma unroll
    for (int g = 0; g < 4; ++g) {
        int pxl = wgrp * 32 + g * 8 + px_sub;
        float* row = s_out + pxl * 65 + dh * 32 + (lane & 3) * 8;
        #pragma unroll
        for (int r = 0; r < 8; ++r) row[r] = acc[g * 8 + r];
    }
    __syncthreads();

    if (valid) {
        const float* srow = s_out + pxslot * 65 + dh * 32;
        const float* bi = bias + dh * 32;
        float* obase = out + (n * 64) * 4096 + (dh * 32) * 4096 + hw;
        #pragma unroll
        for (int i = 0; i < 32; ++i)
            obase[i * 4096] = srow[i] + bi[i];
    }
}

extern "C" void kernel_launch(void* const* d_in, const int* in_sizes, int n_in,
                              void* d_out, int out_size)
{
    const float* B    = (const float*)d_in[0];
    const float* W    = (const float*)d_in[1];
    const float* bias = (const float*)d_in[2];
    float* out = (float*)d_out;

    cvt_kernel<<<1024, 256>>>((const float4*)W);

    cudaFuncSetAttribute(fern_kernel, cudaFuncAttributeMaxDynamicSharedMemorySize, SMEM_BYTES);
    fern_kernel<<<NCTA, TPB, SMEM_BYTES>>>(B, bias, out);
}